// round 2
// baseline (speedup 1.0000x reference)
#include <cuda_runtime.h>
#include <math.h>

#define BB 32
#define TT 4096
#define HH 1024
#define TH (TT * HH)
#define WTHRESH 1e-12f

// Scratch (static device arrays — no runtime allocation)
__device__ float g_scores[TT];
__device__ int   g_nnz;
__device__ int   g_idx[TT];
__device__ float g_w[TT];

// ---------------------------------------------------------------------------
// K1: scores[t] = sum_{b,h} dec[b,h] * enc[b,t,h]
// grid = T blocks, 256 threads; thread tid owns float4 h-slot tid for all b.
// dec (128 KB) becomes L1-resident per SM; enc read is the single 512 MB pass.
// ---------------------------------------------------------------------------
__global__ __launch_bounds__(256) void k1_scores(const float* __restrict__ dec,
                                                 const float* __restrict__ enc) {
    const int t   = blockIdx.x;
    const int tid = threadIdx.x;
    const float4* enc4 = reinterpret_cast<const float4*>(enc);
    const float4* dec4 = reinterpret_cast<const float4*>(dec);

    float p = 0.0f;
    #pragma unroll
    for (int b = 0; b < BB; b++) {
        const float4 e = enc4[b * (TH / 4) + t * (HH / 4) + tid];
        const float4 d = __ldg(&dec4[b * (HH / 4) + tid]);
        p += e.x * d.x + e.y * d.y + e.z * d.z + e.w * d.w;
    }

    // block reduce (256 threads)
    __shared__ float s[8];
    #pragma unroll
    for (int o = 16; o > 0; o >>= 1)
        p += __shfl_down_sync(0xffffffffu, p, o);
    const int lane = tid & 31, w = tid >> 5;
    if (lane == 0) s[w] = p;
    __syncthreads();
    if (w == 0) {
        p = (lane < 8) ? s[lane] : 0.0f;
        #pragma unroll
        for (int o = 4; o > 0; o >>= 1)
            p += __shfl_down_sync(0xffffffffu, p, o);
        if (lane == 0) g_scores[t] = p;
    }
}

// ---------------------------------------------------------------------------
// K2: softmax over T=4096 + deterministic compaction of weights > WTHRESH.
// 1 block, 1024 threads, 4 scores per thread (float4). Compaction uses a
// shfl-based exclusive scan so output order is t-ascending (no atomics).
// ---------------------------------------------------------------------------
__global__ __launch_bounds__(1024) void k2_softmax_compact() {
    __shared__ float red[32];
    __shared__ float bcast;
    __shared__ int   woff[32];

    const int tid  = threadIdx.x;
    const int lane = tid & 31;
    const int w    = tid >> 5;

    float4 sc = reinterpret_cast<const float4*>(g_scores)[tid];

    // ---- block max ----
    float m = fmaxf(fmaxf(sc.x, sc.y), fmaxf(sc.z, sc.w));
    #pragma unroll
    for (int o = 16; o > 0; o >>= 1)
        m = fmaxf(m, __shfl_down_sync(0xffffffffu, m, o));
    if (lane == 0) red[w] = m;
    __syncthreads();
    if (w == 0) {
        m = red[lane];
        #pragma unroll
        for (int o = 16; o > 0; o >>= 1)
            m = fmaxf(m, __shfl_down_sync(0xffffffffu, m, o));
        if (lane == 0) bcast = m;
    }
    __syncthreads();
    const float M = bcast;
    __syncthreads();   // protect red[] reuse below

    // ---- exp + block sum ----
    float4 e;
    e.x = __expf(sc.x - M);
    e.y = __expf(sc.y - M);
    e.z = __expf(sc.z - M);
    e.w = __expf(sc.w - M);
    float sm = e.x + e.y + e.z + e.w;
    #pragma unroll
    for (int o = 16; o > 0; o >>= 1)
        sm += __shfl_down_sync(0xffffffffu, sm, o);
    if (lane == 0) red[w] = sm;
    __syncthreads();
    if (w == 0) {
        sm = red[lane];
        #pragma unroll
        for (int o = 16; o > 0; o >>= 1)
            sm += __shfl_down_sync(0xffffffffu, sm, o);
        if (lane == 0) bcast = sm;
    }
    __syncthreads();
    const float inv = 1.0f / bcast;

    float4 wt;
    wt.x = e.x * inv; wt.y = e.y * inv; wt.z = e.z * inv; wt.w = e.w * inv;

    // ---- deterministic compaction of wt > WTHRESH ----
    const int f0 = wt.x > WTHRESH;
    const int f1 = wt.y > WTHRESH;
    const int f2 = wt.z > WTHRESH;
    const int f3 = wt.w > WTHRESH;
    const int cnt = f0 + f1 + f2 + f3;

    // warp inclusive scan of cnt
    int inc = cnt;
    #pragma unroll
    for (int o = 1; o < 32; o <<= 1) {
        int v = __shfl_up_sync(0xffffffffu, inc, o);
        if (lane >= o) inc += v;
    }
    if (lane == 31) woff[w] = inc;
    __syncthreads();
    if (w == 0) {
        int v = woff[lane];      // 32 warp totals
        int i2 = v;
        #pragma unroll
        for (int o = 1; o < 32; o <<= 1) {
            int u = __shfl_up_sync(0xffffffffu, i2, o);
            if (lane >= o) i2 += u;
        }
        woff[lane] = i2 - v;     // exclusive warp offset
        if (lane == 31) g_nnz = i2;
    }
    __syncthreads();

    int o = woff[w] + (inc - cnt);   // this thread's exclusive offset
    const int t0 = tid * 4;
    if (f0) { g_idx[o] = t0 + 0; g_w[o] = wt.x; o++; }
    if (f1) { g_idx[o] = t0 + 1; g_w[o] = wt.y; o++; }
    if (f2) { g_idx[o] = t0 + 2; g_w[o] = wt.z; o++; }
    if (f3) { g_idx[o] = t0 + 3; g_w[o] = wt.w; o++; }
}

// ---------------------------------------------------------------------------
// K3: out[b,h] = sum over compacted t of w[t] * enc[b,t,h].
// grid = 32 blocks (one per b), 256 threads (thread tid owns float4 h-slot).
// Reads only nnz * 128 KB of enc (typically ~1 MB total).
// ---------------------------------------------------------------------------
__global__ __launch_bounds__(256) void k3_context(const float* __restrict__ enc,
                                                  float* __restrict__ out) {
    const int b   = blockIdx.x;
    const int tid = threadIdx.x;
    const int nnz = g_nnz;

    const float4* enc4 = reinterpret_cast<const float4*>(enc) + b * (TH / 4);
    float4 acc = make_float4(0.f, 0.f, 0.f, 0.f);

    for (int i = 0; i < nnz; i++) {
        const int   t  = g_idx[i];
        const float wt = g_w[i];
        const float4 e = enc4[t * (HH / 4) + tid];
        acc.x += wt * e.x;
        acc.y += wt * e.y;
        acc.z += wt * e.z;
        acc.w += wt * e.w;
    }
    reinterpret_cast<float4*>(out)[b * (HH / 4) + tid] = acc;
}

// ---------------------------------------------------------------------------
extern "C" void kernel_launch(void* const* d_in, const int* in_sizes, int n_in,
                              void* d_out, int out_size) {
    // Identify inputs by element count (dec: 32768, enc: 134217728)
    const float* dec = (const float*)d_in[0];
    const float* enc = (const float*)d_in[1];
    if (n_in >= 2 && in_sizes[0] > in_sizes[1]) {
        dec = (const float*)d_in[1];
        enc = (const float*)d_in[0];
    }
    float* out = (float*)d_out;

    k1_scores<<<TT, 256>>>(dec, enc);
    k2_softmax_compact<<<1, 1024>>>();
    k3_context<<<BB, 256>>>(enc, out);
}

// round 8
// speedup vs baseline: 1.0622x; 1.0622x over previous
#include <cuda_runtime.h>
#include <math.h>

#define BB 32
#define TT 4096
#define HH 1024
#define TH (TT * HH)
#define WTHRESH 1e-12f

// Scratch (static device arrays — no runtime allocation)
__device__ float g_scores[TT];
__device__ int   g_nnz;
__device__ int   g_idx[TT];
__device__ float g_w[TT];

// ---------------------------------------------------------------------------
// K1: scores[t] = sum_{b,h} dec[b,h] * enc[b,t,h]
// 2 t-values per block (grid = T/2), 256 threads; thread tid owns float4
// h-slot tid for all b, for both t's. Dual accumulators double per-thread MLP
// and halve dec L1 traffic per enc byte. __ldcs streams enc past L2.
// ---------------------------------------------------------------------------
__global__ __launch_bounds__(256, 4) void k1_scores(const float* __restrict__ dec,
                                                    const float* __restrict__ enc) {
    const int t0  = blockIdx.x * 2;
    const int tid = threadIdx.x;
    const float4* encA = reinterpret_cast<const float4*>(enc) + t0 * (HH / 4) + tid;
    const float4* encB = encA + (HH / 4);
    const float4* dec4 = reinterpret_cast<const float4*>(dec) + tid;

    float pa = 0.0f, pb = 0.0f;
    #pragma unroll
    for (int b = 0; b < BB; b++) {
        const float4 d  = __ldg (dec4 + b * (HH / 4));
        const float4 ea = __ldcs(encA + b * (TH / 4));
        const float4 eb = __ldcs(encB + b * (TH / 4));
        pa += ea.x * d.x + ea.y * d.y + ea.z * d.z + ea.w * d.w;
        pb += eb.x * d.x + eb.y * d.y + eb.z * d.z + eb.w * d.w;
    }

    // dual block reduce (256 threads)
    __shared__ float sa[8], sb[8];
    #pragma unroll
    for (int o = 16; o > 0; o >>= 1) {
        pa += __shfl_down_sync(0xffffffffu, pa, o);
        pb += __shfl_down_sync(0xffffffffu, pb, o);
    }
    const int lane = tid & 31, w = tid >> 5;
    if (lane == 0) { sa[w] = pa; sb[w] = pb; }
    __syncthreads();
    if (w == 0) {
        pa = (lane < 8) ? sa[lane] : 0.0f;
        pb = (lane < 8) ? sb[lane] : 0.0f;
        #pragma unroll
        for (int o = 4; o > 0; o >>= 1) {
            pa += __shfl_down_sync(0xffffffffu, pa, o);
            pb += __shfl_down_sync(0xffffffffu, pb, o);
        }
        if (lane == 0) {
            g_scores[t0]     = pa;
            g_scores[t0 + 1] = pb;
        }
    }
}

// ---------------------------------------------------------------------------
// K2: softmax over T=4096 + deterministic compaction of weights > WTHRESH.
// 1 block, 1024 threads, 4 scores per thread (float4). Compaction uses a
// shfl-based exclusive scan so output order is t-ascending (no atomics).
// ---------------------------------------------------------------------------
__global__ __launch_bounds__(1024) void k2_softmax_compact() {
    __shared__ float red[32];
    __shared__ float bcast;
    __shared__ int   woff[32];

    const int tid  = threadIdx.x;
    const int lane = tid & 31;
    const int w    = tid >> 5;

    float4 sc = reinterpret_cast<const float4*>(g_scores)[tid];

    // ---- block max ----
    float m = fmaxf(fmaxf(sc.x, sc.y), fmaxf(sc.z, sc.w));
    #pragma unroll
    for (int o = 16; o > 0; o >>= 1)
        m = fmaxf(m, __shfl_down_sync(0xffffffffu, m, o));
    if (lane == 0) red[w] = m;
    __syncthreads();
    if (w == 0) {
        m = red[lane];
        #pragma unroll
        for (int o = 16; o > 0; o >>= 1)
            m = fmaxf(m, __shfl_down_sync(0xffffffffu, m, o));
        if (lane == 0) bcast = m;
    }
    __syncthreads();
    const float M = bcast;
    __syncthreads();   // protect red[] reuse below

    // ---- exp + block sum ----
    float4 e;
    e.x = __expf(sc.x - M);
    e.y = __expf(sc.y - M);
    e.z = __expf(sc.z - M);
    e.w = __expf(sc.w - M);
    float sm = e.x + e.y + e.z + e.w;
    #pragma unroll
    for (int o = 16; o > 0; o >>= 1)
        sm += __shfl_down_sync(0xffffffffu, sm, o);
    if (lane == 0) red[w] = sm;
    __syncthreads();
    if (w == 0) {
        sm = red[lane];
        #pragma unroll
        for (int o = 16; o > 0; o >>= 1)
            sm += __shfl_down_sync(0xffffffffu, sm, o);
        if (lane == 0) bcast = sm;
    }
    __syncthreads();
    const float inv = 1.0f / bcast;

    float4 wt;
    wt.x = e.x * inv; wt.y = e.y * inv; wt.z = e.z * inv; wt.w = e.w * inv;

    // ---- deterministic compaction of wt > WTHRESH ----
    const int f0 = wt.x > WTHRESH;
    const int f1 = wt.y > WTHRESH;
    const int f2 = wt.z > WTHRESH;
    const int f3 = wt.w > WTHRESH;
    const int cnt = f0 + f1 + f2 + f3;

    // warp inclusive scan of cnt
    int inc = cnt;
    #pragma unroll
    for (int o = 1; o < 32; o <<= 1) {
        int v = __shfl_up_sync(0xffffffffu, inc, o);
        if (lane >= o) inc += v;
    }
    if (lane == 31) woff[w] = inc;
    __syncthreads();
    if (w == 0) {
        int v = woff[lane];      // 32 warp totals
        int i2 = v;
        #pragma unroll
        for (int o = 1; o < 32; o <<= 1) {
            int u = __shfl_up_sync(0xffffffffu, i2, o);
            if (lane >= o) i2 += u;
        }
        woff[lane] = i2 - v;     // exclusive warp offset
        if (lane == 31) g_nnz = i2;
    }
    __syncthreads();

    int o = woff[w] + (inc - cnt);   // this thread's exclusive offset
    const int t0 = tid * 4;
    if (f0) { g_idx[o] = t0 + 0; g_w[o] = wt.x; o++; }
    if (f1) { g_idx[o] = t0 + 1; g_w[o] = wt.y; o++; }
    if (f2) { g_idx[o] = t0 + 2; g_w[o] = wt.z; o++; }
    if (f3) { g_idx[o] = t0 + 3; g_w[o] = wt.w; o++; }
}

// ---------------------------------------------------------------------------
// K3: out[b,h] = sum over compacted t of w[t] * enc[b,t,h].
// grid = 32 blocks (one per b), 256 threads (thread tid owns float4 h-slot).
// Reads only nnz * 128 KB of enc (typically ~1 MB total).
// ---------------------------------------------------------------------------
__global__ __launch_bounds__(256) void k3_context(const float* __restrict__ enc,
                                                  float* __restrict__ out) {
    const int b   = blockIdx.x;
    const int tid = threadIdx.x;
    const int nnz = g_nnz;

    const float4* enc4 = reinterpret_cast<const float4*>(enc) + b * (TH / 4);
    float4 acc = make_float4(0.f, 0.f, 0.f, 0.f);

    for (int i = 0; i < nnz; i++) {
        const int   t  = g_idx[i];
        const float wt = g_w[i];
        const float4 e = enc4[t * (HH / 4) + tid];
        acc.x += wt * e.x;
        acc.y += wt * e.y;
        acc.z += wt * e.z;
        acc.w += wt * e.w;
    }
    reinterpret_cast<float4*>(out)[b * (HH / 4) + tid] = acc;
}

// ---------------------------------------------------------------------------
extern "C" void kernel_launch(void* const* d_in, const int* in_sizes, int n_in,
                              void* d_out, int out_size) {
    // Identify inputs by element count (dec: 32768, enc: 134217728)
    const float* dec = (const float*)d_in[0];
    const float* enc = (const float*)d_in[1];
    if (n_in >= 2 && in_sizes[0] > in_sizes[1]) {
        dec = (const float*)d_in[1];
        enc = (const float*)d_in[0];
    }
    float* out = (float*)d_out;

    k1_scores<<<TT / 2, 256>>>(dec, enc);
    k2_softmax_compact<<<1, 1024>>>();
    k3_context<<<BB, 256>>>(enc, out);
}